// round 4
// baseline (speedup 1.0000x reference)
#include <cuda_runtime.h>

#define Dd     64
#define WROW   132            // padded SMEM row stride (floats): 528B, 16B-aligned, bank-spread
#define HALF   512
#define NB     4              // batches per CTA
#define NT     256
#define PIPE   5              // W buffers in flight
#define BUFF   (Dd * WROW)    // floats per W buffer
#define SM_WF  (PIPE * BUFF)
#define SM_VF  (2 * NB * 68)
#define SMEM_BYTES ((SM_WF + SM_VF) * 4)

__device__ float g_vL[64 * Dd];
__device__ float g_wR[64 * Dd];

__device__ __forceinline__ unsigned su(const void* p) {
    return (unsigned)__cvta_generic_to_shared(p);
}
__device__ __forceinline__ void cp16(unsigned d, const float* s) {
    asm volatile("cp.async.cg.shared.global [%0], [%1], 16;" :: "r"(d), "l"(s) : "memory");
}
__device__ __forceinline__ unsigned long long pk2(float a, float b) {
    unsigned long long r;
    asm("mov.b64 %0, {%1,%2};" : "=l"(r) : "f"(a), "f"(b));
    return r;
}
__device__ __forceinline__ unsigned long long fma2(unsigned long long a,
                                                   unsigned long long b,
                                                   unsigned long long c) {
    unsigned long long d;
    asm("fma.rn.f32x2 %0, %1, %2, %3;" : "=l"(d) : "l"(a), "l"(b), "l"(c));
    return d;
}
__device__ __forceinline__ float2 up2(unsigned long long v) {
    float2 f;
    asm("mov.b64 {%0,%1}, %2;" : "=f"(f.x), "=f"(f.y) : "l"(v));
    return f;
}

// Stage one 64x128-float W site (32KB) into padded SMEM rows (8 chunks/thread).
__device__ __forceinline__ void stageW(float* dst, const float* src, int t) {
#pragma unroll
    for (int k = 0; k < 8; k++) {
        int c   = t + k * NT;          // 0..2047 16B chunks
        int row = c >> 5;
        int col = (c & 31) << 2;
        cp16(su(dst + row * WROW + col), src + row * 128 + col);
    }
}

template <int SIDE>
__global__ void __launch_bounds__(NT, 1)
chain_kernel(const float* __restrict__ x, const float* __restrict__ W)
{
    extern __shared__ float sm[];
    float* Wb   = sm;                  // [PIPE][64*WROW]
    float* vbuf = sm + SM_WF;          // [2][NB][68]

    const int t  = threadIdx.x;
    const int gb = blockIdx.x * NB;
    const int bl = t & 3;
    const int q  = t >> 2;

    for (int i = t; i < 2 * NB * 68; i += NT) vbuf[i] = 0.f;
    __syncthreads();
    if (t < NB) vbuf[t * 68] = 1.f;    // boundary vector e0 (both ping buffers zeroed; only buf0 needs e0)

    // prologue: stage first PIPE-1 sites
#pragma unroll
    for (int p = 0; p < PIPE - 1; ++p) {
        int s = SIDE ? (HALF - 1 - p) : p;
        stageW(Wb + p * BUFF, W + s * 8192, t);
        asm volatile("cp.async.commit_group;" ::: "memory");
    }

    const float* xb = x + (gb + bl) * 2048;
    float last = 0.f;
    int buf = 0;

    for (int i = 0; i < HALF; ++i) {
        const int sl    = SIDE ? (HALF - 1 - i) : i;
        const int gsite = SIDE ? (HALF + sl)    : sl;
        const float* Wc = Wb + buf * BUFF;

        asm volatile("cp.async.wait_group %0;" :: "n"(PIPE - 2) : "memory");
        __syncthreads();

        const float* vin  = vbuf + (i & 1) * (NB * 68) + bl * 68;
        float*       vout = vbuf + ((i & 1) ^ 1) * (NB * 68);
        const float2 xv   = *(const float2*)(xb + gsite * 2);   // issued early, used late

        unsigned long long a0 = 0ull, a1 = 0ull;
        if (SIDE == 0) {
            // v_new[q] = x0 * sum_l v[l]*W0[l,q] + x1 * sum_l v[l]*W1[l,q]
#pragma unroll
            for (int l = 0; l < Dd; l += 2) {
                float2 vl = *(const float2*)(vin + l);
                unsigned long long w0 = *(const unsigned long long*)(Wc + l * WROW + 2 * q);
                unsigned long long w1 = *(const unsigned long long*)(Wc + (l + 1) * WROW + 2 * q);
                a0 = fma2(pk2(vl.x, vl.x), w0, a0);
                a1 = fma2(pk2(vl.y, vl.y), w1, a1);
            }
        } else {
            // w_new[q] = x0 * sum_r W0[q,r]*w[r] + x1 * sum_r W1[q,r]*w[r]
            const float* Wrow = Wc + q * WROW;
#pragma unroll
            for (int j = 0; j < 32; j++) {
                float2 wr = *(const float2*)(vin + 2 * j);
                ulonglong2 ww = *(const ulonglong2*)(Wrow + 4 * j);
                a0 = fma2(pk2(wr.x, wr.x), ww.x, a0);
                a1 = fma2(pk2(wr.y, wr.y), ww.y, a1);
            }
        }
        float2 A0 = up2(a0), A1 = up2(a1);
        last = xv.x * (A0.x + A1.x) + xv.y * (A0.y + A1.y);
        vout[bl * 68 + q] = last;

        // prefetch site i+PIPE-1 (distance PIPE-2 steps); ALWAYS commit so
        // wait_group PIPE-2 keeps meaning "buffer for current step is ready"
        if (i + PIPE - 1 < HALF) {
            int sn = SIDE ? (HALF - 1 - (i + PIPE - 1)) : (i + PIPE - 1);
            int bn = buf + PIPE - 1; if (bn >= PIPE) bn -= PIPE;
            stageW(Wb + bn * BUFF, W + sn * 8192, t);
        }
        asm volatile("cp.async.commit_group;" ::: "memory");

        if (++buf == PIPE) buf = 0;
    }

    if (SIDE == 0) g_vL[(gb + bl) * Dd + q] = last;
    else           g_wR[(gb + bl) * Dd + q] = last;
}

// out[b,o] = sum_{l,r} vL[b,l] * core[o,l,r] * wR[b,r]
// one block per batch, warp o computes output o; lane owns columns r=lane, r=lane+32
__global__ void __launch_bounds__(320, 4)
combine_kernel(const float* __restrict__ core, float* __restrict__ out)
{
    __shared__ float vsh[Dd], wsh[Dd];
    const int b    = blockIdx.x;
    const int t    = threadIdx.x;
    const int o    = t >> 5;           // 0..9
    const int lane = t & 31;

    if (t < Dd) { vsh[t] = g_vL[b * Dd + t]; wsh[t] = g_wR[b * Dd + t]; }
    __syncthreads();

    const float* co = core + o * (Dd * Dd);
    float a0 = 0.f, a1 = 0.f;
#pragma unroll 8
    for (int l = 0; l < Dd; ++l) {
        float vl = vsh[l];
        a0 = fmaf(vl, co[l * Dd + lane],      a0);
        a1 = fmaf(vl, co[l * Dd + lane + 32], a1);
    }
    float p = a0 * wsh[lane] + a1 * wsh[lane + 32];
#pragma unroll
    for (int off = 16; off; off >>= 1)
        p += __shfl_down_sync(0xffffffffu, p, off);
    if (lane == 0) out[b * 10 + o] = p;
}

extern "C" void kernel_launch(void* const* d_in, const int* in_sizes, int n_in,
                              void* d_out, int out_size)
{
    const float* x    = (const float*)d_in[0];
    const float* Wl   = (const float*)d_in[1];
    const float* core = (const float*)d_in[2];
    const float* Wr   = (const float*)d_in[3];
    float* out = (float*)d_out;

    cudaFuncSetAttribute(chain_kernel<0>,
                         cudaFuncAttributeMaxDynamicSharedMemorySize, SMEM_BYTES);
    cudaFuncSetAttribute(chain_kernel<1>,
                         cudaFuncAttributeMaxDynamicSharedMemorySize, SMEM_BYTES);

    chain_kernel<0><<<16, NT, SMEM_BYTES>>>(x, Wl);
    chain_kernel<1><<<16, NT, SMEM_BYTES>>>(x, Wr);
    combine_kernel<<<64, 320>>>(core, out);
}

// round 5
// speedup vs baseline: 1.9301x; 1.9301x over previous
#include <cuda_runtime.h>

#define Dd     64
#define WROW   132            // padded SMEM row stride (floats): 528B, 16B-aligned
#define HALF   512
#define NB     2              // batches per CTA
#define NT     256
#define PIPE   5              // W buffers in flight
#define BUFF   (Dd * WROW)
#define SM_WF  (PIPE * BUFF)
#define SM_VF  (2 * NB * 68)
#define SMEM_BYTES ((SM_WF + SM_VF) * 4)

typedef unsigned long long u64;

__device__ float g_vL[64 * Dd];
__device__ float g_wR[64 * Dd];

__device__ __forceinline__ unsigned su(const void* p) {
    return (unsigned)__cvta_generic_to_shared(p);
}
__device__ __forceinline__ void cp16(unsigned d, const float* s) {
    asm volatile("cp.async.cg.shared.global [%0], [%1], 16;" :: "r"(d), "l"(s) : "memory");
}
__device__ __forceinline__ u64 pk2(float a, float b) {
    u64 r; asm("mov.b64 %0, {%1,%2};" : "=l"(r) : "f"(a), "f"(b)); return r;
}
__device__ __forceinline__ u64 fma2(u64 a, u64 b, u64 c) {
    u64 d; asm("fma.rn.f32x2 %0, %1, %2, %3;" : "=l"(d) : "l"(a), "l"(b), "l"(c)); return d;
}
__device__ __forceinline__ float2 up2(u64 v) {
    float2 f; asm("mov.b64 {%0,%1}, %2;" : "=f"(f.x), "=f"(f.y) : "l"(v)); return f;
}

// Stage one 64x128-float W site (32KB) into padded SMEM rows (8 chunks/thread).
__device__ __forceinline__ void stageW(float* dst, const float* src, int t) {
#pragma unroll
    for (int k = 0; k < 8; k++) {
        int c   = t + k * NT;          // 0..2047 16B chunks
        int row = c >> 5;
        int col = (c & 31) << 2;
        cp16(su(dst + row * WROW + col), src + row * 128 + col);
    }
}

// Thread layout: t = h | (bl<<1) | (q<<2)
//   h  : half of the contracted index (2-way split, reduced via shfl_xor(1))
//   bl : local batch (NB=2)
//   q  : output lane 0..63
__global__ void __launch_bounds__(NT, 1)
chain_kernel(const float* __restrict__ x, const float* __restrict__ Wl,
             const float* __restrict__ Wr)
{
    extern __shared__ float sm[];
    float* Wb   = sm;                  // [PIPE][64*WROW]
    float* vbuf = sm + SM_WF;          // [2][NB][68]

    const int t    = threadIdx.x;
    const int side = blockIdx.x >> 5;            // 32 CTAs per side
    const int gb   = (blockIdx.x & 31) * NB;
    const int h    = t & 1;
    const int bl   = (t >> 1) & (NB - 1);
    const int q    = t >> 2;
    const float* W = side ? Wr : Wl;

    for (int i = t; i < SM_VF; i += NT) vbuf[i] = 0.f;
    __syncthreads();
    if (t < NB) vbuf[t * 68] = 1.f;    // boundary vector e0 in ping buffer 0

    // prologue: stage first PIPE-1 sites
#pragma unroll
    for (int p = 0; p < PIPE - 1; ++p) {
        int s = side ? (HALF - 1 - p) : p;
        stageW(Wb + p * BUFF, W + s * 8192, t);
        asm volatile("cp.async.commit_group;" ::: "memory");
    }

    const float* xb = x + (gb + bl) * 2048;
    float last = 0.f;
    int buf = 0;

    for (int i = 0; i < HALF; ++i) {
        const int sl    = side ? (HALF - 1 - i) : i;
        const int gsite = side ? (HALF + sl)    : sl;
        const float* Wc = Wb + buf * BUFF;

        asm volatile("cp.async.wait_group %0;" :: "n"(PIPE - 2) : "memory");
        __syncthreads();

        const float* vin  = vbuf + (i & 1) * (NB * 68) + bl * 68;
        float*       vout = vbuf + ((i & 1) ^ 1) * (NB * 68);
        const float2 xv   = *(const float2*)(xb + gsite * 2);

        u64 a0 = 0ull, a1 = 0ull;
        if (side == 0) {
            // v_new[q] = x . (sum_l v[l]*W01[l,q]); this thread: l in [32h, 32h+32)
            const float* vh    = vin + 32 * h;
            const float* Wbase = Wc + (32 * h) * WROW + 2 * q;
#pragma unroll
            for (int l = 0; l < 32; l += 2) {
                float2 vl = *(const float2*)(vh + l);
                u64 w0 = *(const u64*)(Wbase + l * WROW);
                u64 w1 = *(const u64*)(Wbase + (l + 1) * WROW);
                a0 = fma2(pk2(vl.x, vl.x), w0, a0);
                a1 = fma2(pk2(vl.y, vl.y), w1, a1);
            }
        } else {
            // w_new[q] = x . (sum_r W01[q,r]*w[r]); this thread: r in [32h, 32h+32)
            const float* vh   = vin + 32 * h;
            const float* Wrow = Wc + q * WROW + 64 * h;
#pragma unroll
            for (int j = 0; j < 16; j++) {
                float2 wr = *(const float2*)(vh + 2 * j);
                ulonglong2 ww = *(const ulonglong2*)(Wrow + 4 * j);
                a0 = fma2(pk2(wr.x, wr.x), ww.x, a0);
                a1 = fma2(pk2(wr.y, wr.y), ww.y, a1);
            }
        }
        float2 A0 = up2(a0), A1 = up2(a1);
        float p = xv.x * (A0.x + A1.x) + xv.y * (A0.y + A1.y);
        p += __shfl_xor_sync(0xffffffffu, p, 1);   // combine the two halves
        last = p;
        if (h == 0) vout[bl * 68 + q] = p;

        // prefetch site i+PIPE-1; ALWAYS commit so wait_group stays aligned
        if (i + PIPE - 1 < HALF) {
            int sn = side ? (HALF - 1 - (i + PIPE - 1)) : (i + PIPE - 1);
            int bn = buf + PIPE - 1; if (bn >= PIPE) bn -= PIPE;
            stageW(Wb + bn * BUFF, W + sn * 8192, t);
        }
        asm volatile("cp.async.commit_group;" ::: "memory");

        if (++buf == PIPE) buf = 0;
    }

    if (h == 0) {
        if (side == 0) g_vL[(gb + bl) * Dd + q] = last;
        else           g_wR[(gb + bl) * Dd + q] = last;
    }
}

// out[b,o] = sum_{l,r} vL[b,l] * core[o,l,r] * wR[b,r]
// one block per batch; warp o computes output o; lane owns r=lane, r=lane+32
__global__ void __launch_bounds__(320, 4)
combine_kernel(const float* __restrict__ core, float* __restrict__ out)
{
    __shared__ float vsh[Dd], wsh[Dd];
    const int b    = blockIdx.x;
    const int t    = threadIdx.x;
    const int o    = t >> 5;           // 0..9
    const int lane = t & 31;

    if (t < Dd) { vsh[t] = g_vL[b * Dd + t]; wsh[t] = g_wR[b * Dd + t]; }
    __syncthreads();

    const float* co = core + o * (Dd * Dd);
    float a0 = 0.f, a1 = 0.f;
#pragma unroll 8
    for (int l = 0; l < Dd; ++l) {
        float vl = vsh[l];
        a0 = fmaf(vl, co[l * Dd + lane],      a0);
        a1 = fmaf(vl, co[l * Dd + lane + 32], a1);
    }
    float p = a0 * wsh[lane] + a1 * wsh[lane + 32];
#pragma unroll
    for (int off = 16; off; off >>= 1)
        p += __shfl_down_sync(0xffffffffu, p, off);
    if (lane == 0) out[b * 10 + o] = p;
}

extern "C" void kernel_launch(void* const* d_in, const int* in_sizes, int n_in,
                              void* d_out, int out_size)
{
    const float* x    = (const float*)d_in[0];
    const float* Wl   = (const float*)d_in[1];
    const float* core = (const float*)d_in[2];
    const float* Wr   = (const float*)d_in[3];
    float* out = (float*)d_out;

    cudaFuncSetAttribute(chain_kernel,
                         cudaFuncAttributeMaxDynamicSharedMemorySize, SMEM_BYTES);

    chain_kernel<<<64, NT, SMEM_BYTES>>>(x, Wl, Wr);
    combine_kernel<<<64, 320>>>(core, out);
}